// round 1
// baseline (speedup 1.0000x reference)
#include <cuda_runtime.h>

#define NXD 1024
#define NYD 1024
#define DD  128

// Scratch (static device globals — no allocation in kernel_launch)
__device__ float  g_s[NXD * NYD];
__device__ float  g_rmax[NXD];
__device__ float  g_rinv[NXD];
__device__ float  g_cmax[NYD];
__device__ float  g_cinv[NYD];
__device__ double g_acc[2];

// ---------------------------------------------------------------------------
// Kernel 1: s[i,j] = -sum_d |z_x[i,d] - z_y[j,d]|, 32x32 tiles, smem staging.
// Block: 256 threads. Each thread computes 4 rows x 1 column of the tile.
// ---------------------------------------------------------------------------
__global__ void __launch_bounds__(256) s_kernel(const float* __restrict__ zx,
                                                const float* __restrict__ zy) {
    // zero the global accumulators once per launch (runs before reduce kernel)
    if (blockIdx.x == 0 && blockIdx.y == 0 && threadIdx.x == 0) {
        g_acc[0] = 0.0;
        g_acc[1] = 0.0;
    }

    __shared__ float xs[32 * 128];        // x tile, row-major, broadcast access
    __shared__ float ys[32 * 132];        // y tile, padded row (132) -> conflict-free

    const int tid = threadIdx.x;
    const int i0 = blockIdx.y * 32;
    const int j0 = blockIdx.x * 32;

    const float4* zx4 = (const float4*)(zx + i0 * DD);
    const float4* zy4 = (const float4*)(zy + j0 * DD);

    // cooperative load: 32 rows x 128 floats = 1024 float4s, 4 per thread
    #pragma unroll
    for (int t = tid; t < 1024; t += 256) {
        const int row = t >> 5;       // 32 float4 per row
        const int c4  = t & 31;
        ((float4*)xs)[t] = zx4[t];
        *(float4*)&ys[row * 132 + c4 * 4] = zy4[t];
    }
    __syncthreads();

    const int jj = tid & 31;   // column within tile (varies across warp -> coalesced)
    const int ir = tid >> 5;   // base row 0..7; thread covers ir, ir+8, ir+16, ir+24

    float acc0 = 0.f, acc1 = 0.f, acc2 = 0.f, acc3 = 0.f;

    #pragma unroll 8
    for (int d4 = 0; d4 < 32; d4++) {
        const float4 y  = *(const float4*)&ys[jj * 132 + d4 * 4];
        const float4 x0 = *(const float4*)&xs[(ir     ) * 128 + d4 * 4];
        const float4 x1 = *(const float4*)&xs[(ir +  8) * 128 + d4 * 4];
        const float4 x2 = *(const float4*)&xs[(ir + 16) * 128 + d4 * 4];
        const float4 x3 = *(const float4*)&xs[(ir + 24) * 128 + d4 * 4];

        acc0 += fabsf(x0.x - y.x) + fabsf(x0.y - y.y) + fabsf(x0.z - y.z) + fabsf(x0.w - y.w);
        acc1 += fabsf(x1.x - y.x) + fabsf(x1.y - y.y) + fabsf(x1.z - y.z) + fabsf(x1.w - y.w);
        acc2 += fabsf(x2.x - y.x) + fabsf(x2.y - y.y) + fabsf(x2.z - y.z) + fabsf(x2.w - y.w);
        acc3 += fabsf(x3.x - y.x) + fabsf(x3.y - y.y) + fabsf(x3.z - y.z) + fabsf(x3.w - y.w);
    }

    const int col = j0 + jj;
    g_s[(i0 + ir     ) * NYD + col] = -acc0;
    g_s[(i0 + ir +  8) * NYD + col] = -acc1;
    g_s[(i0 + ir + 16) * NYD + col] = -acc2;
    g_s[(i0 + ir + 24) * NYD + col] = -acc3;
}

// ---------------------------------------------------------------------------
// Kernel 2: row softmax stats. One warp per row. 8 warps/block, 128 blocks.
// ---------------------------------------------------------------------------
__global__ void __launch_bounds__(256) row_stats_kernel() {
    const int warp = threadIdx.x >> 5;
    const int lane = threadIdx.x & 31;
    const int i = blockIdx.x * 8 + warp;
    const float* row = g_s + i * NYD;

    float m = -1e30f;
    #pragma unroll 4
    for (int k = lane; k < NYD; k += 32) m = fmaxf(m, row[k]);
    #pragma unroll
    for (int o = 16; o; o >>= 1) m = fmaxf(m, __shfl_xor_sync(0xffffffffu, m, o));

    float ssum = 0.f;
    #pragma unroll 4
    for (int k = lane; k < NYD; k += 32) ssum += __expf(row[k] - m);
    #pragma unroll
    for (int o = 16; o; o >>= 1) ssum += __shfl_xor_sync(0xffffffffu, ssum, o);

    if (lane == 0) {
        g_rmax[i] = m;
        g_rinv[i] = 1.0f / ssum;
    }
}

// ---------------------------------------------------------------------------
// Kernel 3: column softmax stats. One thread per column (coalesced reads).
// ---------------------------------------------------------------------------
__global__ void __launch_bounds__(256) col_stats_kernel() {
    const int j = blockIdx.x * blockDim.x + threadIdx.x;

    float m = -1e30f;
    #pragma unroll 4
    for (int i = 0; i < NXD; i++) m = fmaxf(m, g_s[i * NYD + j]);

    float ssum = 0.f;
    #pragma unroll 4
    for (int i = 0; i < NXD; i++) ssum += __expf(g_s[i * NYD + j] - m);

    g_cmax[j] = m;
    g_cinv[j] = 1.0f / ssum;
}

// ---------------------------------------------------------------------------
// Kernel 4: fused a/b/combine + weighted reduction (double accumulation).
// ---------------------------------------------------------------------------
__global__ void __launch_bounds__(256) reduce_kernel() {
    double t0 = 0.0, t1 = 0.0;
    const int stride = gridDim.x * blockDim.x;

    for (int idx = blockIdx.x * blockDim.x + threadIdx.x; idx < NXD * NYD; idx += stride) {
        const int i = idx >> 10;
        const int j = idx & 1023;
        const float v = g_s[idx];
        const float a = __expf(v - g_rmax[i]) * g_rinv[i];
        const float b = __expf(v - g_cmax[j]) * g_cinv[j];
        const float comb = a + b - a * b;
        t0 += (double)comb;
        t1 += (double)comb * (double)v;
    }

    __shared__ double s0[256];
    __shared__ double s1[256];
    s0[threadIdx.x] = t0;
    s1[threadIdx.x] = t1;
    __syncthreads();
    #pragma unroll
    for (int o = 128; o; o >>= 1) {
        if (threadIdx.x < o) {
            s0[threadIdx.x] += s0[threadIdx.x + o];
            s1[threadIdx.x] += s1[threadIdx.x + o];
        }
        __syncthreads();
    }
    if (threadIdx.x == 0) {
        atomicAdd(&g_acc[0], s0[0]);
        atomicAdd(&g_acc[1], s1[0]);
    }
}

// ---------------------------------------------------------------------------
// Kernel 5: finalize. c = sum(comb*s)/sum(comb); out = c*theta + beta.
// ---------------------------------------------------------------------------
__global__ void finalize_kernel(const float* __restrict__ theta,
                                const float* __restrict__ beta,
                                float* __restrict__ out, int n) {
    const float c = (float)(g_acc[1] / g_acc[0]);
    const int k = threadIdx.x;
    if (k < n) out[k] = c * theta[k] + beta[k];
}

extern "C" void kernel_launch(void* const* d_in, const int* in_sizes, int n_in,
                              void* d_out, int out_size) {
    const float* zx    = (const float*)d_in[0];  // (1024, 128)
    const float* zy    = (const float*)d_in[1];  // (1024, 128)
    const float* theta = (const float*)d_in[2];  // (1, 4)
    const float* beta  = (const float*)d_in[3];  // (4,)

    dim3 grid(NYD / 32, NXD / 32);
    s_kernel<<<grid, 256>>>(zx, zy);
    row_stats_kernel<<<NXD / 8, 256>>>();
    col_stats_kernel<<<NYD / 256, 256>>>();
    reduce_kernel<<<256, 256>>>();
    finalize_kernel<<<1, 32>>>(theta, beta, (float*)d_out, out_size);
}

// round 4
// speedup vs baseline: 4.5584x; 4.5584x over previous
#include <cuda_runtime.h>

#define NXD 1024
#define NYD 1024
#define DD  128

// Scratch (static device globals — no allocation in kernel_launch)
__device__ float  g_s[NXD * NYD];
__device__ float  g_rmax[NXD];
__device__ float  g_rinv[NXD];
__device__ float  g_cmax[NYD];
__device__ float  g_cinv[NYD];
__device__ double g_acc[2];

// ---------------------------------------------------------------------------
// Kernel 1: s[i,j] = -sum_d |z_x[i,d] - z_y[j,d]|
// Tile: 32 rows x 64 cols. Block: 256 threads, each computes 4 rows x 2 cols.
// ---------------------------------------------------------------------------
__global__ void __launch_bounds__(256) s_kernel(const float* __restrict__ zx,
                                                const float* __restrict__ zy) {
    if (blockIdx.x == 0 && blockIdx.y == 0 && threadIdx.x == 0) {
        g_acc[0] = 0.0;
        g_acc[1] = 0.0;
    }

    __shared__ float xs[32 * 128];   // 32 x rows (broadcast access)
    __shared__ float ys[64 * 132];   // 64 y rows, padded to 132 (conflict-free)

    const int tid = threadIdx.x;
    const int i0 = blockIdx.y * 32;
    const int j0 = blockIdx.x * 64;

    const float4* zx4 = (const float4*)(zx + i0 * DD);
    const float4* zy4 = (const float4*)(zy + j0 * DD);

    #pragma unroll
    for (int t = tid; t < 1024; t += 256)
        ((float4*)xs)[t] = zx4[t];
    #pragma unroll
    for (int t = tid; t < 2048; t += 256) {
        const int row = t >> 5;
        const int c4  = t & 31;
        *(float4*)&ys[row * 132 + c4 * 4] = zy4[t];
    }
    __syncthreads();

    const int jj = tid & 31;   // col within warp (coalesced / conflict-free)
    const int ir = tid >> 5;   // rows ir, ir+8, ir+16, ir+24

    float a00 = 0.f, a10 = 0.f, a20 = 0.f, a30 = 0.f;   // col jj
    float a01 = 0.f, a11 = 0.f, a21 = 0.f, a31 = 0.f;   // col jj+32

    #pragma unroll 8
    for (int d4 = 0; d4 < 32; d4++) {
        const float4 y0 = *(const float4*)&ys[(jj     ) * 132 + d4 * 4];
        const float4 y1 = *(const float4*)&ys[(jj + 32) * 132 + d4 * 4];
        const float4 x0 = *(const float4*)&xs[(ir     ) * 128 + d4 * 4];
        const float4 x1 = *(const float4*)&xs[(ir +  8) * 128 + d4 * 4];
        const float4 x2 = *(const float4*)&xs[(ir + 16) * 128 + d4 * 4];
        const float4 x3 = *(const float4*)&xs[(ir + 24) * 128 + d4 * 4];

        a00 += fabsf(x0.x - y0.x) + fabsf(x0.y - y0.y) + fabsf(x0.z - y0.z) + fabsf(x0.w - y0.w);
        a10 += fabsf(x1.x - y0.x) + fabsf(x1.y - y0.y) + fabsf(x1.z - y0.z) + fabsf(x1.w - y0.w);
        a20 += fabsf(x2.x - y0.x) + fabsf(x2.y - y0.y) + fabsf(x2.z - y0.z) + fabsf(x2.w - y0.w);
        a30 += fabsf(x3.x - y0.x) + fabsf(x3.y - y0.y) + fabsf(x3.z - y0.z) + fabsf(x3.w - y0.w);

        a01 += fabsf(x0.x - y1.x) + fabsf(x0.y - y1.y) + fabsf(x0.z - y1.z) + fabsf(x0.w - y1.w);
        a11 += fabsf(x1.x - y1.x) + fabsf(x1.y - y1.y) + fabsf(x1.z - y1.z) + fabsf(x1.w - y1.w);
        a21 += fabsf(x2.x - y1.x) + fabsf(x2.y - y1.y) + fabsf(x2.z - y1.z) + fabsf(x2.w - y1.w);
        a31 += fabsf(x3.x - y1.x) + fabsf(x3.y - y1.y) + fabsf(x3.z - y1.z) + fabsf(x3.w - y1.w);
    }

    const int c0 = j0 + jj;
    const int c1 = j0 + jj + 32;
    g_s[(i0 + ir     ) * NYD + c0] = -a00;
    g_s[(i0 + ir +  8) * NYD + c0] = -a10;
    g_s[(i0 + ir + 16) * NYD + c0] = -a20;
    g_s[(i0 + ir + 24) * NYD + c0] = -a30;
    g_s[(i0 + ir     ) * NYD + c1] = -a01;
    g_s[(i0 + ir +  8) * NYD + c1] = -a11;
    g_s[(i0 + ir + 16) * NYD + c1] = -a21;
    g_s[(i0 + ir + 24) * NYD + c1] = -a31;
}

// ---------------------------------------------------------------------------
// Kernel 2: fused row + column softmax stats (max and 1/sum).
// Blocks 0..127   : row stats, one warp per row (8 rows/block).
// Blocks 128..159 : col stats, 32 cols/block, 32x8 thread layout.
// ---------------------------------------------------------------------------
__global__ void __launch_bounds__(256) stats_kernel() {
    if (blockIdx.x < 128) {
        // ---- row stats: warp per row ----
        const int warp = threadIdx.x >> 5;
        const int lane = threadIdx.x & 31;
        const int i = blockIdx.x * 8 + warp;
        const float4* row4 = (const float4*)(g_s + i * NYD);

        float m = -1e30f;
        #pragma unroll
        for (int k = lane; k < 256; k += 32) {
            const float4 v = row4[k];
            m = fmaxf(m, fmaxf(fmaxf(v.x, v.y), fmaxf(v.z, v.w)));
        }
        #pragma unroll
        for (int o = 16; o; o >>= 1) m = fmaxf(m, __shfl_xor_sync(0xffffffffu, m, o));

        float ssum = 0.f;
        #pragma unroll
        for (int k = lane; k < 256; k += 32) {
            const float4 v = row4[k];
            ssum += __expf(v.x - m) + __expf(v.y - m) + __expf(v.z - m) + __expf(v.w - m);
        }
        #pragma unroll
        for (int o = 16; o; o >>= 1) ssum += __shfl_xor_sync(0xffffffffu, ssum, o);

        if (lane == 0) {
            g_rmax[i] = m;
            g_rinv[i] = 1.0f / ssum;
        }
    } else {
        // ---- col stats: 32 cols per block, thread (cx, ry) ----
        const int cx = threadIdx.x & 31;
        const int ry = threadIdx.x >> 5;
        const int j = (blockIdx.x - 128) * 32 + cx;

        __shared__ float red[8][33];

        float m = -1e30f;
        #pragma unroll 8
        for (int r = ry; r < NXD; r += 8) m = fmaxf(m, g_s[r * NYD + j]);
        red[ry][cx] = m;
        __syncthreads();
        if (ry == 0) {
            #pragma unroll
            for (int t = 1; t < 8; t++) m = fmaxf(m, red[t][cx]);
            red[0][cx] = m;
        }
        __syncthreads();
        m = red[0][cx];
        __syncthreads();

        float ssum = 0.f;
        #pragma unroll 8
        for (int r = ry; r < NXD; r += 8) ssum += __expf(g_s[r * NYD + j] - m);
        red[ry][cx] = ssum;
        __syncthreads();
        if (ry == 0) {
            #pragma unroll
            for (int t = 1; t < 8; t++) ssum += red[t][cx];
            g_cmax[j] = m;
            g_cinv[j] = 1.0f / ssum;
        }
    }
}

// ---------------------------------------------------------------------------
// Kernel 3: fused a/b/combine + weighted reduction (fp32 partials, fp64 atomics).
// ---------------------------------------------------------------------------
__global__ void __launch_bounds__(256) reduce_kernel() {
    float t0 = 0.f, t1 = 0.f;
    const int stride = gridDim.x * blockDim.x;

    for (int idx = blockIdx.x * blockDim.x + threadIdx.x; idx < NXD * NYD; idx += stride) {
        const int i = idx >> 10;
        const int j = idx & 1023;
        const float v = g_s[idx];
        const float a = __expf(v - g_rmax[i]) * g_rinv[i];
        const float b = __expf(v - g_cmax[j]) * g_cinv[j];
        const float comb = a + b - a * b;
        t0 += comb;
        t1 += comb * v;
    }

    // warp reduce
    #pragma unroll
    for (int o = 16; o; o >>= 1) {
        t0 += __shfl_xor_sync(0xffffffffu, t0, o);
        t1 += __shfl_xor_sync(0xffffffffu, t1, o);
    }

    __shared__ float s0[8], s1[8];
    const int warp = threadIdx.x >> 5;
    const int lane = threadIdx.x & 31;
    if (lane == 0) { s0[warp] = t0; s1[warp] = t1; }
    __syncthreads();
    if (threadIdx.x == 0) {
        double d0 = 0.0, d1 = 0.0;
        #pragma unroll
        for (int w = 0; w < 8; w++) { d0 += (double)s0[w]; d1 += (double)s1[w]; }
        atomicAdd(&g_acc[0], d0);
        atomicAdd(&g_acc[1], d1);
    }
}

// ---------------------------------------------------------------------------
// Kernel 4: finalize. c = sum(comb*s)/sum(comb); out = c*theta + beta.
// ---------------------------------------------------------------------------
__global__ void finalize_kernel(const float* __restrict__ theta,
                                const float* __restrict__ beta,
                                float* __restrict__ out, int n) {
    const float c = (float)(g_acc[1] / g_acc[0]);
    const int k = threadIdx.x;
    if (k < n) out[k] = c * theta[k] + beta[k];
}

extern "C" void kernel_launch(void* const* d_in, const int* in_sizes, int n_in,
                              void* d_out, int out_size) {
    const float* zx    = (const float*)d_in[0];  // (1024, 128)
    const float* zy    = (const float*)d_in[1];  // (1024, 128)
    const float* theta = (const float*)d_in[2];  // (1, 4)
    const float* beta  = (const float*)d_in[3];  // (4,)

    dim3 grid(NYD / 64, NXD / 32);
    s_kernel<<<grid, 256>>>(zx, zy);
    stats_kernel<<<160, 256>>>();
    reduce_kernel<<<512, 256>>>();
    finalize_kernel<<<1, 32>>>(theta, beta, (float*)d_out, out_size);
}